// round 1
// baseline (speedup 1.0000x reference)
#include <cuda_runtime.h>
#include <math.h>

// Problem constants
#define BB 64
#define SS 1024
#define HH 128
#define AA 8
#define WIN 5
#define PADW 2
#define STILE 128
#define NCHUNK (SS / STILE)   // 8
#define DP 129                // smem pitch (odd -> conflict-free stride access)
#define GW 8                  // padded window stride for float4 loads

// Scratch (no allocations allowed)
__device__ float gG[AA * HH * GW];                   // [a][h][w(pad 8)]
__device__ float gLogits[AA * BB * SS];              // [a][b][s]
__device__ float gCtxPart[NCHUNK * AA * BB * HH];    // [sc][a][b][h]

// ---------------------------------------------------------------------------
// K1: G[a,h,w] = sum_f P[a,h,f] * E[a,f,w]     (E = aspEmbed_weight reshaped)
// grid = A, block = 128 (thread = h)
// ---------------------------------------------------------------------------
__global__ void k_prep(const float* __restrict__ P, const float* __restrict__ E) {
    extern __shared__ float sm[];
    float* Psm = sm;              // [128][DP]
    float* Esm = sm + HH * DP;    // [H*WIN]
    int a = blockIdx.x, t = threadIdx.x;

    const float* Pa = P + (size_t)a * HH * HH;
    for (int r = 0; r < HH; ++r)
        Psm[r * DP + t] = Pa[(size_t)r * HH + t];           // coalesced
    for (int i = t; i < HH * WIN; i += HH)
        Esm[i] = E[(size_t)a * HH * WIN + i];
    __syncthreads();

    int h = t;
    float g[WIN] = {0.f, 0.f, 0.f, 0.f, 0.f};
    for (int f = 0; f < HH; ++f) {
        float pf = Psm[h * DP + f];                         // stride DP -> conflict-free
        #pragma unroll
        for (int w = 0; w < WIN; ++w) g[w] += pf * Esm[f * WIN + w];
    }
    #pragma unroll
    for (int w = 0; w < WIN; ++w) gG[(a * HH + h) * GW + w] = g[w];
    #pragma unroll
    for (int w = WIN; w < GW; ++w) gG[(a * HH + h) * GW + w] = 0.f;
}

// ---------------------------------------------------------------------------
// K2: logits[a,b,s] = sum_w sum_h doc[b, s+w-2, h] * G[a,h,w]   (zero-padded)
// grid = (S/STILE, B), block = 128 (thread = local s)
// ---------------------------------------------------------------------------
__global__ void k_logits(const float* __restrict__ doc) {
    extern __shared__ float sm[];
    float* dsm = sm;                         // [(STILE+4)][DP]
    float* Gsm = sm + (STILE + 4) * DP;      // [A*H*GW]
    int b  = blockIdx.y;
    int s0 = blockIdx.x * STILE;
    int t  = threadIdx.x;

    for (int i = t; i < AA * HH * GW; i += HH) Gsm[i] = gG[i];

    const float* db = doc + (size_t)b * SS * HH;
    for (int r = 0; r < STILE + 4; ++r) {
        int gs = s0 - PADW + r;
        dsm[r * DP + t] = (gs >= 0 && gs < SS) ? db[(size_t)gs * HH + t] : 0.f;
    }
    __syncthreads();

    float acc[AA] = {};
    for (int h = 0; h < HH; ++h) {
        float d0 = dsm[(t + 0) * DP + h];    // stride DP across warp -> conflict-free
        float d1 = dsm[(t + 1) * DP + h];
        float d2 = dsm[(t + 2) * DP + h];
        float d3 = dsm[(t + 3) * DP + h];
        float d4 = dsm[(t + 4) * DP + h];
        #pragma unroll
        for (int a = 0; a < AA; ++a) {
            const float4 g = *reinterpret_cast<const float4*>(&Gsm[(a * HH + h) * GW]);
            const float g4 = Gsm[(a * HH + h) * GW + 4];    // broadcast loads
            acc[a] += d0 * g.x + d1 * g.y + d2 * g.z + d3 * g.w + d4 * g4;
        }
    }
    #pragma unroll
    for (int a = 0; a < AA; ++a)
        gLogits[((size_t)a * BB + b) * SS + s0 + t] = acc[a];
}

// ---------------------------------------------------------------------------
// K3: attn = softmax_s(logits); write to out[b][a][s]
// grid = A*B (row = a*B + b), block = 256
// ---------------------------------------------------------------------------
__global__ void k_softmax(float* __restrict__ out) {
    int row = blockIdx.x;
    int a = row >> 6;          // / BB
    int b = row & 63;          // % BB
    const float* lg = gLogits + (size_t)row * SS;
    int t = threadIdx.x;

    float v[4];
    float m = -3.4e38f;
    #pragma unroll
    for (int i = 0; i < 4; ++i) { v[i] = lg[t + i * 256]; m = fmaxf(m, v[i]); }

    __shared__ float redm[8];
    #pragma unroll
    for (int o = 16; o > 0; o >>= 1) m = fmaxf(m, __shfl_xor_sync(0xffffffffu, m, o));
    if ((t & 31) == 0) redm[t >> 5] = m;
    __syncthreads();
    m = redm[0];
    #pragma unroll
    for (int i = 1; i < 8; ++i) m = fmaxf(m, redm[i]);

    float sl = 0.f;
    #pragma unroll
    for (int i = 0; i < 4; ++i) { v[i] = __expf(v[i] - m); sl += v[i]; }
    __shared__ float reds[8];
    #pragma unroll
    for (int o = 16; o > 0; o >>= 1) sl += __shfl_xor_sync(0xffffffffu, sl, o);
    if ((t & 31) == 0) reds[t >> 5] = sl;
    __syncthreads();
    float tot = 0.f;
    #pragma unroll
    for (int i = 0; i < 8; ++i) tot += reds[i];
    float inv = 1.0f / tot;

    float* op = out + ((size_t)b * AA + a) * SS;
    #pragma unroll
    for (int i = 0; i < 4; ++i) op[t + i * 256] = v[i] * inv;
}

// ---------------------------------------------------------------------------
// K4: ctx partials: gCtxPart[sc][a][b][h] = sum_{s in chunk} attn[a,b,s]*doc[b,s,h]
// grid = (NCHUNK, B), block = 128 (thread = h). Deterministic (no atomics).
// ---------------------------------------------------------------------------
__global__ void k_ctx(const float* __restrict__ doc, const float* __restrict__ attn) {
    int b = blockIdx.y, sc = blockIdx.x;
    int t = threadIdx.x;
    __shared__ float asmem[AA * STILE];
    #pragma unroll
    for (int a = 0; a < AA; ++a)
        asmem[a * STILE + t] = attn[((size_t)b * AA + a) * SS + sc * STILE + t];
    __syncthreads();

    const float* dp = doc + ((size_t)b * SS + sc * STILE) * HH + t;
    float acc[AA] = {};
    for (int s = 0; s < STILE; ++s) {
        float d = dp[(size_t)s * HH];        // coalesced across t
        #pragma unroll
        for (int a = 0; a < AA; ++a) acc[a] += d * asmem[a * STILE + s];  // broadcast
    }
    #pragma unroll
    for (int a = 0; a < AA; ++a)
        gCtxPart[(((size_t)sc * AA + a) * BB + b) * HH + t] = acc[a];
}

// ---------------------------------------------------------------------------
// K5: rep[b,a,f] = sum_h ctx[a,b,h] * P[a,h,f], ctx reduced over chunks
// grid = B*A (blk = b*A + a), block = 128 (thread = f)
// ---------------------------------------------------------------------------
__global__ void k_rep(const float* __restrict__ P, float* __restrict__ out) {
    int blk = blockIdx.x;
    int a = blk & 7, b = blk >> 3;
    int f = threadIdx.x;
    __shared__ float csm[HH];
    float c = 0.f;
    #pragma unroll
    for (int sc = 0; sc < NCHUNK; ++sc)
        c += gCtxPart[(((size_t)sc * AA + a) * BB + b) * HH + f];
    csm[f] = c;
    __syncthreads();

    float acc = 0.f;
    const float* Pp = P + (size_t)a * HH * HH + f;
    for (int h = 0; h < HH; ++h) acc += csm[h] * Pp[(size_t)h * HH];  // coalesced

    out[(size_t)BB * AA * SS + ((size_t)b * AA + a) * HH + f] = acc;
}

// ---------------------------------------------------------------------------
extern "C" void kernel_launch(void* const* d_in, const int* in_sizes, int n_in,
                              void* d_out, int out_size) {
    const float* doc = (const float*)d_in[0];   // (B,S,H)
    const float* E   = (const float*)d_in[1];   // (A, WIN*H)
    const float* P   = (const float*)d_in[2];   // (A,H,H)
    float* out = (float*)d_out;                 // [attn (B,A,S) | rep (B,A,H)]

    size_t sm1 = (size_t)(HH * DP + HH * WIN) * sizeof(float);           // ~68.6 KB
    size_t sm2 = (size_t)((STILE + 4) * DP + AA * HH * GW) * sizeof(float); // ~100.9 KB
    cudaFuncSetAttribute(k_prep,   cudaFuncAttributeMaxDynamicSharedMemorySize, (int)sm1);
    cudaFuncSetAttribute(k_logits, cudaFuncAttributeMaxDynamicSharedMemorySize, (int)sm2);

    k_prep<<<AA, HH, sm1>>>(P, E);
    k_logits<<<dim3(SS / STILE, BB), HH, sm2>>>(doc);
    k_softmax<<<AA * BB, 256>>>(out);
    k_ctx<<<dim3(NCHUNK, BB), HH>>>(doc, out);
    k_rep<<<BB * AA, HH>>>(P, out);
}

// round 3
// speedup vs baseline: 1.4623x; 1.4623x over previous
#include <cuda_runtime.h>
#include <math.h>

// Problem constants
#define BB 64
#define SS 1024
#define HH 128
#define AA 8
#define WIN 5
#define PADW 2
#define STILE 128            // s-tile for logits kernel
#define CTILE 64             // s-chunk for ctx kernel
#define NCHUNK (SS / CTILE)  // 16
#define DP 129               // smem pitch (odd -> conflict-free strided access)

// Scratch (no allocations allowed)
// Packed G: [h][w][8] with inner order (a0,a4,a1,a5,a2,a6,a3,a7) so that a
// 16B load yields two 64-bit (G[a],G[a+4]) pairs for fma.rn.f32x2.
__device__ float4 gGp4[HH * WIN * 2];                // 128*5*8 floats
__device__ float gLogits[AA * BB * SS];              // [a][b][s]
__device__ float gCtxPart[NCHUNK * AA * BB * HH];    // [sc][a][b][h]

__device__ __forceinline__ void fma2(unsigned long long& acc,
                                     unsigned long long d2,
                                     unsigned long long g2) {
    asm("fma.rn.f32x2 %0, %1, %2, %3;" : "=l"(acc) : "l"(d2), "l"(g2), "l"(acc));
}
__device__ __forceinline__ unsigned long long dup2(float v) {
    unsigned long long r;
    asm("mov.b64 %0, {%1, %1};" : "=l"(r) : "f"(v));
    return r;
}

// ---------------------------------------------------------------------------
// K1: G[a,h,w] = sum_f P[a,h,f] * E[a,f,w]; scatter into packed layout gGp4.
// grid = A, block = 128 (thread = h)
// ---------------------------------------------------------------------------
__global__ void k_prep(const float* __restrict__ P, const float* __restrict__ E) {
    extern __shared__ float sm[];
    float* Psm = sm;              // [128][DP]
    float* Esm = sm + HH * DP;    // [H*WIN]
    int a = blockIdx.x, t = threadIdx.x;

    const float* Pa = P + (size_t)a * HH * HH;
    for (int r = 0; r < HH; ++r)
        Psm[r * DP + t] = Pa[(size_t)r * HH + t];           // coalesced
    for (int i = t; i < HH * WIN; i += HH)
        Esm[i] = E[(size_t)a * HH * WIN + i];
    __syncthreads();

    int h = t;
    float g[WIN] = {0.f, 0.f, 0.f, 0.f, 0.f};
    for (int f = 0; f < HH; ++f) {
        float pf = Psm[h * DP + f];                         // conflict-free
        #pragma unroll
        for (int w = 0; w < WIN; ++w) g[w] += pf * Esm[f * WIN + w];
    }
    float* Gp = (float*)gGp4;
    #pragma unroll
    for (int w = 0; w < WIN; ++w)
        Gp[(h * WIN + w) * 8 + (a & 3) * 2 + (a >> 2)] = g[w];
}

// ---------------------------------------------------------------------------
// K2: logits[a,b,s] = sum_w sum_h doc[b, s+w-2, h] * G[a,h,w]
// Packed f32x2: 4 accumulator pairs (a, a+4). grid = (S/STILE, B), block=128.
// ---------------------------------------------------------------------------
__global__ void __launch_bounds__(128) k_logits(const float* __restrict__ doc) {
    extern __shared__ float sm[];
    float* dsm = sm;                         // [(STILE+4)][DP]
    float* Gsm = sm + (STILE + 4) * DP;      // [H*WIN*8] packed pairs
    int b  = blockIdx.y;
    int s0 = blockIdx.x * STILE;
    int t  = threadIdx.x;
    int wid = t >> 5, lane = t & 31;

    // Copy packed G (5120 floats) via float4
    {
        const float4* src = gGp4;
        float4* dst = (float4*)Gsm;
        #pragma unroll
        for (int i = t; i < HH * WIN * 2; i += HH) dst[i] = src[i];
    }

    // Tile fill: each warp loads one full row (128 floats) via float4.
    const float* db = doc + (size_t)b * SS * HH;
    for (int r0 = 0; r0 < STILE + 4; r0 += 4) {
        int row = r0 + wid;
        int gs = s0 - PADW + row;
        float4 v = make_float4(0.f, 0.f, 0.f, 0.f);
        if (gs >= 0 && gs < SS)
            v = *(const float4*)&db[(size_t)gs * HH + 4 * lane];
        float* d = &dsm[row * DP + 4 * lane];
        d[0] = v.x; d[1] = v.y; d[2] = v.z; d[3] = v.w;
    }
    __syncthreads();

    unsigned long long acc[4] = {0ull, 0ull, 0ull, 0ull};   // (0.f,0.f) pairs
    #pragma unroll 2
    for (int h = 0; h < HH; ++h) {
        // 5 window taps of doc, duplicated into both f32x2 lanes
        unsigned long long dd[WIN];
        #pragma unroll
        for (int w = 0; w < WIN; ++w)
            dd[w] = dup2(dsm[(t + w) * DP + h]);            // stride DP: conflict-free
        const float* gh = &Gsm[h * (WIN * 8)];
        #pragma unroll
        for (int w = 0; w < WIN; ++w) {
            ulonglong2 g01 = *(const ulonglong2*)(gh + w * 8);      // broadcast LDS.128
            ulonglong2 g23 = *(const ulonglong2*)(gh + w * 8 + 4);
            fma2(acc[0], dd[w], g01.x);
            fma2(acc[1], dd[w], g01.y);
            fma2(acc[2], dd[w], g23.x);
            fma2(acc[3], dd[w], g23.y);
        }
    }

    #pragma unroll
    for (int p = 0; p < 4; ++p) {
        float lo, hi;
        asm("mov.b64 {%0, %1}, %2;" : "=f"(lo), "=f"(hi) : "l"(acc[p]));
        gLogits[((size_t)p       * BB + b) * SS + s0 + t] = lo;
        gLogits[((size_t)(p + 4) * BB + b) * SS + s0 + t] = hi;
    }
}

// ---------------------------------------------------------------------------
// K3: attn = softmax_s(logits); write to out[b][a][s]
// grid = A*B (row = a*B + b), block = 256
// ---------------------------------------------------------------------------
__global__ void k_softmax(float* __restrict__ out) {
    int row = blockIdx.x;
    int a = row >> 6;
    int b = row & 63;
    const float* lg = gLogits + (size_t)row * SS;
    int t = threadIdx.x;

    float v[4];
    float m = -3.4e38f;
    #pragma unroll
    for (int i = 0; i < 4; ++i) { v[i] = lg[t + i * 256]; m = fmaxf(m, v[i]); }

    __shared__ float redm[8];
    #pragma unroll
    for (int o = 16; o > 0; o >>= 1) m = fmaxf(m, __shfl_xor_sync(0xffffffffu, m, o));
    if ((t & 31) == 0) redm[t >> 5] = m;
    __syncthreads();
    m = redm[0];
    #pragma unroll
    for (int i = 1; i < 8; ++i) m = fmaxf(m, redm[i]);

    float sl = 0.f;
    #pragma unroll
    for (int i = 0; i < 4; ++i) { v[i] = __expf(v[i] - m); sl += v[i]; }
    __shared__ float reds[8];
    #pragma unroll
    for (int o = 16; o > 0; o >>= 1) sl += __shfl_xor_sync(0xffffffffu, sl, o);
    if ((t & 31) == 0) reds[t >> 5] = sl;
    __syncthreads();
    float tot = 0.f;
    #pragma unroll
    for (int i = 0; i < 8; ++i) tot += reds[i];
    float inv = 1.0f / tot;

    float* op = out + ((size_t)b * AA + a) * SS;
    #pragma unroll
    for (int i = 0; i < 4; ++i) op[t + i * 256] = v[i] * inv;
}

// ---------------------------------------------------------------------------
// K4: ctx partials over 64-s chunks (grid = (16, B)) for occupancy/BW.
// gCtxPart[sc][a][b][h] = sum_{s in chunk} attn[a,b,s]*doc[b,s,h]
// ---------------------------------------------------------------------------
__global__ void __launch_bounds__(128, 8) k_ctx(const float* __restrict__ doc,
                                                const float* __restrict__ attn) {
    int b = blockIdx.y, sc = blockIdx.x;
    int t = threadIdx.x;
    __shared__ float asmem[AA * CTILE];
    if (t < CTILE) {
        #pragma unroll
        for (int a = 0; a < AA; ++a)
            asmem[a * CTILE + t] = attn[((size_t)b * AA + a) * SS + sc * CTILE + t];
    }
    __syncthreads();

    const float* dp = doc + ((size_t)b * SS + sc * CTILE) * HH + t;
    float acc[AA] = {};
    #pragma unroll 8
    for (int s = 0; s < CTILE; ++s) {
        float d = dp[(size_t)s * HH];        // coalesced across t
        #pragma unroll
        for (int a = 0; a < AA; ++a) acc[a] += d * asmem[a * CTILE + s];  // broadcast
    }
    #pragma unroll
    for (int a = 0; a < AA; ++a)
        gCtxPart[(((size_t)sc * AA + a) * BB + b) * HH + t] = acc[a];
}

// ---------------------------------------------------------------------------
// K5: rep[b,a,f] = sum_h ctx[a,b,h] * P[a,h,f], ctx reduced over chunks
// grid = B*A (blk = b*A + a), block = 128 (thread = f)
// ---------------------------------------------------------------------------
__global__ void k_rep(const float* __restrict__ P, float* __restrict__ out) {
    int blk = blockIdx.x;
    int a = blk & 7, b = blk >> 3;
    int f = threadIdx.x;
    __shared__ float csm[HH];
    float c = 0.f;
    #pragma unroll
    for (int sc = 0; sc < NCHUNK; ++sc)
        c += gCtxPart[(((size_t)sc * AA + a) * BB + b) * HH + f];
    csm[f] = c;
    __syncthreads();

    float acc = 0.f;
    const float* Pp = P + (size_t)a * HH * HH + f;
    for (int h = 0; h < HH; ++h) acc += csm[h] * Pp[(size_t)h * HH];  // coalesced

    out[(size_t)BB * AA * SS + ((size_t)b * AA + a) * HH + f] = acc;
}

// ---------------------------------------------------------------------------
extern "C" void kernel_launch(void* const* d_in, const int* in_sizes, int n_in,
                              void* d_out, int out_size) {
    const float* doc = (const float*)d_in[0];   // (B,S,H)
    const float* E   = (const float*)d_in[1];   // (A, WIN*H)
    const float* P   = (const float*)d_in[2];   // (A,H,H)
    float* out = (float*)d_out;                 // [attn (B,A,S) | rep (B,A,H)]

    size_t sm1 = (size_t)(HH * DP + HH * WIN) * sizeof(float);               // ~68.6 KB
    size_t sm2 = (size_t)((STILE + 4) * DP + HH * WIN * 8) * sizeof(float);  // ~88.6 KB
    cudaFuncSetAttribute(k_prep,   cudaFuncAttributeMaxDynamicSharedMemorySize, (int)sm1);
    cudaFuncSetAttribute(k_logits, cudaFuncAttributeMaxDynamicSharedMemorySize, (int)sm2);

    k_prep<<<AA, HH, sm1>>>(P, E);
    k_logits<<<dim3(SS / STILE, BB), HH, sm2>>>(doc);
    k_softmax<<<AA * BB, 256>>>(out);
    k_ctx<<<dim3(NCHUNK, BB), HH>>>(doc, out);
    k_rep<<<BB * AA, HH>>>(P, out);
}

// round 5
// speedup vs baseline: 1.6861x; 1.1531x over previous
#include <cuda_runtime.h>
#include <math.h>

// Problem constants
#define BB 64
#define SS 1024
#define HH 128
#define AA 8
#define WIN 5
#define PADW 2
#define STILE 128            // s-tile for logits kernel
#define CTILE 64             // s-chunk per ctx block
#define NSUB 4               // s-subgroups per ctx block
#define NCHF (SS / CTILE * NSUB)   // 64 fine chunks
#define DPK 129              // k_prep smem pitch

// Scratch (no allocations allowed)
// Packed G: [h][w][8] with inner order (a0,a4,a1,a5,a2,a6,a3,a7) so a 16B load
// yields two 64-bit (G[a],G[a+4]) pairs for fma.rn.f32x2.
__device__ float4 gGp4[HH * WIN * 2];                // 128*5*8 floats
__device__ float gLogits[AA * BB * SS];              // [a][b][s]
__device__ float gCtxPart[NCHF * AA * BB * HH];      // [scf][a][b][h]  (16.8MB)

__device__ __forceinline__ void fma2(unsigned long long& acc,
                                     unsigned long long d2,
                                     unsigned long long g2) {
    asm("fma.rn.f32x2 %0, %1, %2, %3;" : "=l"(acc) : "l"(d2), "l"(g2), "l"(acc));
}
__device__ __forceinline__ unsigned long long dup2(float v) {
    unsigned long long r;
    asm("mov.b64 %0, {%1, %1};" : "=l"(r) : "f"(v));
    return r;
}
__device__ __forceinline__ void unpk(unsigned long long p, float& lo, float& hi) {
    asm("mov.b64 {%0, %1}, %2;" : "=f"(lo), "=f"(hi) : "l"(p));
}

// ---------------------------------------------------------------------------
// K1: G[a,h,w] = sum_f P[a,h,f] * E[a,f,w]; scatter into packed layout gGp4.
// grid = A, block = 128 (thread = h)
// ---------------------------------------------------------------------------
__global__ void k_prep(const float* __restrict__ P, const float* __restrict__ E) {
    extern __shared__ float sm[];
    float* Psm = sm;               // [128][DPK]
    float* Esm = sm + HH * DPK;    // [H*WIN]
    int a = blockIdx.x, t = threadIdx.x;

    const float* Pa = P + (size_t)a * HH * HH;
    for (int r = 0; r < HH; ++r)
        Psm[r * DPK + t] = Pa[(size_t)r * HH + t];
    for (int i = t; i < HH * WIN; i += HH)
        Esm[i] = E[(size_t)a * HH * WIN + i];
    __syncthreads();

    int h = t;
    float g[WIN] = {0.f, 0.f, 0.f, 0.f, 0.f};
    for (int f = 0; f < HH; ++f) {
        float pf = Psm[h * DPK + f];
        #pragma unroll
        for (int w = 0; w < WIN; ++w) g[w] += pf * Esm[f * WIN + w];
    }
    float* Gp = (float*)gGp4;
    #pragma unroll
    for (int w = 0; w < WIN; ++w)
        Gp[(h * WIN + w) * 8 + (a & 3) * 2 + (a >> 2)] = g[w];
}

// ---------------------------------------------------------------------------
// K2: logits[a,b,s] = sum_w sum_h doc[b, s+w-2, h] * G[a,h,w]
// Org: lane -> 4 consecutive s, warp -> 32-h split, f32x2 accumulators.
// dsm: pitch 128 with XOR swizzle col = h ^ ((row>>2)&31)  (conflict-free for
// both the stride-32 scalar writes and the stride-4-row tap reads).
// grid = (S/STILE, B), block = 128.
// ---------------------------------------------------------------------------
__global__ void __launch_bounds__(128) k_logits(const float* __restrict__ doc) {
    extern __shared__ float sm[];
    float* dsm = sm;                         // [(STILE+4)][128] swizzled
    float* Gsm = sm + (STILE + 4) * HH;      // [H*WIN*8] packed pairs
    int b  = blockIdx.y;
    int s0 = blockIdx.x * STILE;
    int t  = threadIdx.x;
    int wid = t >> 5, lane = t & 31;

    // Copy packed G (5120 floats) via float4
    {
        const float4* src = gGp4;
        float4* dst = (float4*)Gsm;
        #pragma unroll
        for (int i = t; i < HH * WIN * 2; i += HH) dst[i] = src[i];
    }

    // Tile fill: warp handles rows wid, wid+4, ... Lane l loads cols l+32m
    // (coalesced) and stores swizzled (conflict-free scalar STS).
    const float* db = doc + (size_t)b * SS * HH;
    for (int row = wid; row < STILE + 4; row += 4) {
        int gs = s0 - PADW + row;
        int swz = (row >> 2) & 31;
        const float* src = db + (size_t)gs * HH;
        #pragma unroll
        for (int m = 0; m < 4; ++m) {
            int c = lane + 32 * m;
            float v = (gs >= 0 && gs < SS) ? src[c] : 0.f;
            dsm[row * HH + (c ^ swz)] = v;
        }
    }
    __syncthreads();

    // Main loop: this warp's h-range, lane's 4 consecutive s.
    int h0 = wid * 32;
    int st0 = 4 * lane;
    unsigned long long acc[4][4];
    #pragma unroll
    for (int i = 0; i < 4; ++i)
        #pragma unroll
        for (int p = 0; p < 4; ++p) acc[i][p] = 0ull;

    #pragma unroll 2
    for (int hh = 0; hh < 32; ++hh) {
        int h = h0 + hh;
        unsigned long long d[8];
        #pragma unroll
        for (int r = 0; r < 8; ++r) {
            int row = st0 + r;
            d[r] = dup2(dsm[row * HH + (h ^ ((row >> 2) & 31))]);
        }
        const float* gh = &Gsm[h * (WIN * 8)];
        #pragma unroll
        for (int w = 0; w < WIN; ++w) {
            ulonglong2 g01 = *(const ulonglong2*)(gh + w * 8);
            ulonglong2 g23 = *(const ulonglong2*)(gh + w * 8 + 4);
            #pragma unroll
            for (int si = 0; si < 4; ++si) {
                fma2(acc[si][0], d[si + w], g01.x);
                fma2(acc[si][1], d[si + w], g01.y);
                fma2(acc[si][2], d[si + w], g23.x);
                fma2(acc[si][3], d[si + w], g23.y);
            }
        }
    }

    // Cross-warp h-reduction: red[st][33] (pitch 33), slot = a*4 + wid.
    __syncthreads();
    float* red = sm;   // 128*33 floats = 16.9KB, fits in dsm region
    #pragma unroll
    for (int si = 0; si < 4; ++si) {
        int st = st0 + si;
        #pragma unroll
        for (int p = 0; p < 4; ++p) {
            float lo, hi;
            unpk(acc[si][p], lo, hi);
            red[st * 33 + p * 4 + wid] = lo;           // aspect p
            red[st * 33 + (p + 4) * 4 + wid] = hi;     // aspect p+4
        }
    }
    __syncthreads();

    int st = t;
    #pragma unroll
    for (int a = 0; a < AA; ++a) {
        const float* rp = &red[st * 33 + a * 4];
        float v = rp[0] + rp[1] + rp[2] + rp[3];
        gLogits[((size_t)a * BB + b) * SS + s0 + st] = v;
    }
}

// ---------------------------------------------------------------------------
// K3: attn = softmax_s(logits); write to out[b][a][s]
// grid = A*B (row = a*B + b), block = 256
// ---------------------------------------------------------------------------
__global__ void k_softmax(float* __restrict__ out) {
    int row = blockIdx.x;
    int a = row >> 6;
    int b = row & 63;
    const float* lg = gLogits + (size_t)row * SS;
    int t = threadIdx.x;

    float v[4];
    float m = -3.4e38f;
    #pragma unroll
    for (int i = 0; i < 4; ++i) { v[i] = lg[t + i * 256]; m = fmaxf(m, v[i]); }

    __shared__ float redm[8];
    #pragma unroll
    for (int o = 16; o > 0; o >>= 1) m = fmaxf(m, __shfl_xor_sync(0xffffffffu, m, o));
    if ((t & 31) == 0) redm[t >> 5] = m;
    __syncthreads();
    m = redm[0];
    #pragma unroll
    for (int i = 1; i < 8; ++i) m = fmaxf(m, redm[i]);

    float sl = 0.f;
    #pragma unroll
    for (int i = 0; i < 4; ++i) { v[i] = __expf(v[i] - m); sl += v[i]; }
    __shared__ float reds[8];
    #pragma unroll
    for (int o = 16; o > 0; o >>= 1) sl += __shfl_xor_sync(0xffffffffu, sl, o);
    if ((t & 31) == 0) reds[t >> 5] = sl;
    __syncthreads();
    float tot = 0.f;
    #pragma unroll
    for (int i = 0; i < 8; ++i) tot += reds[i];
    float inv = 1.0f / tot;

    float* op = out + ((size_t)b * AA + a) * SS;
    #pragma unroll
    for (int i = 0; i < 4; ++i) op[t + i * 256] = v[i] * inv;
}

// ---------------------------------------------------------------------------
// K4: ctx partials, float4 loads. Thread = (h-quad = t&31, s-sub = t>>5).
// gCtxPart[sc*4+sg][a][b][h] = sum_{s in chunk, s%4==sg} attn[a,b,s]*doc[b,s,h]
// grid = (S/CTILE, B) = (16, 64), block = 128.
// ---------------------------------------------------------------------------
__global__ void __launch_bounds__(128, 8) k_ctx(const float* __restrict__ doc,
                                                const float* __restrict__ attn) {
    int b = blockIdx.y, sc = blockIdx.x;
    int t = threadIdx.x;
    int hq = t & 31, sg = t >> 5;

    __shared__ float asmem[AA * CTILE];
    #pragma unroll
    for (int i = t; i < AA * CTILE; i += 128) {
        int a = i >> 6, s = i & 63;
        asmem[i] = attn[((size_t)b * AA + a) * SS + sc * CTILE + s];
    }
    __syncthreads();

    const float4* dp = (const float4*)(doc + ((size_t)b * SS + sc * CTILE) * HH) + hq;
    unsigned long long acc[AA][2];
    #pragma unroll
    for (int a = 0; a < AA; ++a) { acc[a][0] = 0ull; acc[a][1] = 0ull; }

    #pragma unroll 4
    for (int s = sg; s < CTILE; s += NSUB) {
        float4 dv = dp[s * (HH / 4)];            // coalesced LDG.128
        unsigned long long dxy, dzw;
        asm("mov.b64 %0, {%1, %2};" : "=l"(dxy) : "f"(dv.x), "f"(dv.y));
        asm("mov.b64 %0, {%1, %2};" : "=l"(dzw) : "f"(dv.z), "f"(dv.w));
        #pragma unroll
        for (int a = 0; a < AA; ++a) {
            unsigned long long av = dup2(asmem[a * CTILE + s]);  // broadcast
            fma2(acc[a][0], dxy, av);
            fma2(acc[a][1], dzw, av);
        }
    }

    int scf = sc * NSUB + sg;
    #pragma unroll
    for (int a = 0; a < AA; ++a) {
        float4 o;
        unpk(acc[a][0], o.x, o.y);
        unpk(acc[a][1], o.z, o.w);
        float4* op = (float4*)(gCtxPart + (((size_t)scf * AA + a) * BB + b) * HH) + hq;
        *op = o;                                  // coalesced STG.128
    }
}

// ---------------------------------------------------------------------------
// K5: rep[b,a,f] = sum_h ctx[a,b,h] * P[a,h,f], ctx reduced over 64 partials
// grid = B*A (blk = b*A + a), block = 128 (thread = f)
// ---------------------------------------------------------------------------
__global__ void k_rep(const float* __restrict__ P, float* __restrict__ out) {
    int blk = blockIdx.x;
    int a = blk & 7, b = blk >> 3;
    int f = threadIdx.x;
    __shared__ float csm[HH];
    float c = 0.f;
    #pragma unroll 8
    for (int scf = 0; scf < NCHF; ++scf)
        c += gCtxPart[(((size_t)scf * AA + a) * BB + b) * HH + f];
    csm[f] = c;
    __syncthreads();

    float acc = 0.f;
    const float* Pp = P + (size_t)a * HH * HH + f;
    for (int h = 0; h < HH; ++h) acc += csm[h] * Pp[(size_t)h * HH];

    out[(size_t)BB * AA * SS + ((size_t)b * AA + a) * HH + f] = acc;
}

// ---------------------------------------------------------------------------
extern "C" void kernel_launch(void* const* d_in, const int* in_sizes, int n_in,
                              void* d_out, int out_size) {
    const float* doc = (const float*)d_in[0];   // (B,S,H)
    const float* E   = (const float*)d_in[1];   // (A, WIN*H)
    const float* P   = (const float*)d_in[2];   // (A,H,H)
    float* out = (float*)d_out;                 // [attn (B,A,S) | rep (B,A,H)]

    size_t sm1 = (size_t)(HH * DPK + HH * WIN) * sizeof(float);              // ~68.6 KB
    size_t sm2 = (size_t)((STILE + 4) * HH + HH * WIN * 8) * sizeof(float);  // ~88.1 KB
    cudaFuncSetAttribute(k_prep,   cudaFuncAttributeMaxDynamicSharedMemorySize, (int)sm1);
    cudaFuncSetAttribute(k_logits, cudaFuncAttributeMaxDynamicSharedMemorySize, (int)sm2);

    k_prep<<<AA, HH, sm1>>>(P, E);
    k_logits<<<dim3(SS / STILE, BB), HH, sm2>>>(doc);
    k_softmax<<<AA * BB, 256>>>(out);
    k_ctx<<<dim3(SS / CTILE, BB), HH>>>(doc, out);
    k_rep<<<BB * AA, HH>>>(P, out);
}